// round 1
// baseline (speedup 1.0000x reference)
#include <cuda_runtime.h>

#define BB 16
#define LL 1024
#define FF 512
#define HH 8
#define DD 64

// Scratch (device globals — no allocation allowed in kernel_launch)
__device__ float g_q[BB*HH*LL*DD];
__device__ float g_k[BB*HH*LL*DD];
__device__ float g_v[BB*HH*LL*DD];
__device__ float g_x[BB*LL*HH*DD];

// ---------------------------------------------------------------------------
// Generic SGEMM: C = A(M,K) @ W(K,N) + bias
// mode 0: C row-major [M,N]
// mode 1: scatter to (B,H,L,D) layout: C[((b*H+h)*L + l)*D + d]
// BM=BN=128, BK=8, 256 threads, 8x8 per-thread tile.
// ---------------------------------------------------------------------------
__global__ void __launch_bounds__(256) gemm_kernel(
    const float* __restrict__ A, const float* __restrict__ W,
    const float* __restrict__ bias, float* __restrict__ C,
    int M, int N, int K, int mode)
{
    __shared__ float As[8][128];
    __shared__ float Bs[8][128];

    const int t  = threadIdx.x;
    const int bm = blockIdx.y * 128;
    const int bn = blockIdx.x * 128;
    const int tm = (t >> 4) * 8;
    const int tn = (t & 15) * 8;

    const int ar = t >> 1;         // A tile row (0..127)
    const int ac = (t & 1) * 4;    // A tile col (0 or 4)
    const int wr = t >> 5;         // W tile row (0..7)
    const int wc = (t & 31) * 4;   // W tile col

    const float* Ap = A + (size_t)(bm + ar) * K + ac;
    const float* Wp = W + (size_t)wr * N + bn + wc;

    float acc[8][8];
    #pragma unroll
    for (int i = 0; i < 8; i++)
        #pragma unroll
        for (int j = 0; j < 8; j++) acc[i][j] = 0.f;

    for (int k0 = 0; k0 < K; k0 += 8) {
        float4 av = *(const float4*)Ap; Ap += 8;
        float4 wv = *(const float4*)Wp; Wp += (size_t)8 * N;

        __syncthreads();
        As[ac + 0][ar] = av.x;
        As[ac + 1][ar] = av.y;
        As[ac + 2][ar] = av.z;
        As[ac + 3][ar] = av.w;
        *(float4*)&Bs[wr][wc] = wv;
        __syncthreads();

        #pragma unroll
        for (int kk = 0; kk < 8; kk++) {
            float a[8], b[8];
            *(float4*)(a    ) = *(const float4*)&As[kk][tm];
            *(float4*)(a + 4) = *(const float4*)&As[kk][tm + 4];
            *(float4*)(b    ) = *(const float4*)&Bs[kk][tn];
            *(float4*)(b + 4) = *(const float4*)&Bs[kk][tn + 4];
            #pragma unroll
            for (int i = 0; i < 8; i++)
                #pragma unroll
                for (int j = 0; j < 8; j++)
                    acc[i][j] += a[i] * b[j];
        }
    }

    if (mode == 0) {
        #pragma unroll
        for (int i = 0; i < 8; i++) {
            int gm = bm + tm + i;
            float* cp = C + (size_t)gm * N + bn + tn;
            #pragma unroll
            for (int j = 0; j < 8; j++)
                cp[j] = acc[i][j] + bias[bn + tn + j];
        }
    } else {
        #pragma unroll
        for (int i = 0; i < 8; i++) {
            int gm = bm + tm + i;
            int b_ = gm >> 10;       // L = 1024
            int l_ = gm & 1023;
            #pragma unroll
            for (int j = 0; j < 8; j++) {
                int gn = bn + tn + j;
                int h_ = gn >> 6;    // D = 64
                int d_ = gn & 63;
                C[(((size_t)(b_ * HH + h_)) * LL + l_) * DD + d_] = acc[i][j] + bias[gn];
            }
        }
    }
}

// ---------------------------------------------------------------------------
// Flash attention with toeplitz bias.
// One CTA per (q-tile of 64, h, b). 256 threads = 16x16 grid, 4x4 S per thread.
// smem tiles use stride PAD=65 for (near) conflict-free access.
// ---------------------------------------------------------------------------
#define PAD 65

__global__ void __launch_bounds__(256) attn_kernel(
    const float* __restrict__ q, const float* __restrict__ k,
    const float* __restrict__ v, const float* __restrict__ toep,
    float* __restrict__ x)
{
    extern __shared__ float sm[];
    float* Qs = sm;                 // [64][PAD]  q-tile, row-major (row, d)
    float* Kt = Qs + 64 * PAD;      // [64][PAD]  k-tile TRANSPOSED: (d, key)
    float* Vs = Kt + 64 * PAD;      // [64][PAD]  v-tile, (key, d)
    float* Ps = Vs + 64 * PAD;      // [64][PAD]  probabilities (row, key)
    float* Tp = Ps + 64 * PAD;      // [4096]     toeplitz row for this head

    const int t  = threadIdx.x;
    const int qt = blockIdx.x;
    const int h  = blockIdx.y;
    const int b  = blockIdx.z;
    const int bh = b * HH + h;

    const float* qb = q + (size_t)bh * LL * DD + (size_t)qt * 64 * DD;
    const float* kb = k + (size_t)bh * LL * DD;
    const float* vb = v + (size_t)bh * LL * DD;

    // Load Q tile + toeplitz row
    for (int idx = t; idx < 4096; idx += 256) {
        int r = idx >> 6, d = idx & 63;
        Qs[r * PAD + d] = qb[idx];
        Tp[idx] = toep[(size_t)h * 4096 + idx];
    }

    const int ty = t >> 4;   // 0..15 -> rows ty*4 .. ty*4+3
    const int tx = t & 15;   // 0..15 -> cols tx*4 .. tx*4+3

    float m_[4], l_[4], o[4][4];
    #pragma unroll
    for (int i = 0; i < 4; i++) {
        m_[i] = -1e30f; l_[i] = 0.f;
        #pragma unroll
        for (int c = 0; c < 4; c++) o[i][c] = 0.f;
    }

    int qxi[4], qyi[4];
    #pragma unroll
    for (int i = 0; i < 4; i++) {
        int qr = qt * 64 + ty * 4 + i;
        qxi[i] = qr >> 5;     // NY = 32
        qyi[i] = qr & 31;
    }

    const float scale = 0.125f;   // 1/sqrt(64)

    for (int kt = 0; kt < 16; kt++) {
        const float* kp = kb + (size_t)kt * 64 * DD;
        const float* vp = vb + (size_t)kt * 64 * DD;
        for (int idx = t; idx < 4096; idx += 256) {
            int r = idx >> 6, d = idx & 63;
            Kt[d * PAD + r] = kp[idx];       // transposed
            Vs[r * PAD + d] = vp[idx];
        }
        __syncthreads();

        // S = Q @ K^T  (per-thread 4x4)
        float s[4][4];
        #pragma unroll
        for (int i = 0; i < 4; i++)
            #pragma unroll
            for (int j = 0; j < 4; j++) s[i][j] = 0.f;

        #pragma unroll 8
        for (int d = 0; d < 64; d++) {
            float a0 = Qs[(ty * 4 + 0) * PAD + d];
            float a1 = Qs[(ty * 4 + 1) * PAD + d];
            float a2 = Qs[(ty * 4 + 2) * PAD + d];
            float a3 = Qs[(ty * 4 + 3) * PAD + d];
            float b0 = Kt[d * PAD + tx * 4 + 0];
            float b1 = Kt[d * PAD + tx * 4 + 1];
            float b2 = Kt[d * PAD + tx * 4 + 2];
            float b3 = Kt[d * PAD + tx * 4 + 3];
            s[0][0] += a0 * b0; s[0][1] += a0 * b1; s[0][2] += a0 * b2; s[0][3] += a0 * b3;
            s[1][0] += a1 * b0; s[1][1] += a1 * b1; s[1][2] += a1 * b2; s[1][3] += a1 * b3;
            s[2][0] += a2 * b0; s[2][1] += a2 * b1; s[2][2] += a2 * b2; s[2][3] += a2 * b3;
            s[3][0] += a3 * b0; s[3][1] += a3 * b1; s[3][2] += a3 * b2; s[3][3] += a3 * b3;
        }

        // scale + toeplitz bias
        #pragma unroll
        for (int i = 0; i < 4; i++) {
            #pragma unroll
            for (int j = 0; j < 4; j++) {
                int kc = kt * 64 + tx * 4 + j;
                int dx = qxi[i] - (kc >> 5) + 32;
                int dy = qyi[i] - (kc & 31) + 32;
                s[i][j] = s[i][j] * scale + Tp[dx * 64 + dy];
            }
        }

        // online softmax (per row, reduce across the 16 tx-lanes)
        #pragma unroll
        for (int i = 0; i < 4; i++) {
            float tmax = fmaxf(fmaxf(s[i][0], s[i][1]), fmaxf(s[i][2], s[i][3]));
            #pragma unroll
            for (int off = 8; off >= 1; off >>= 1)
                tmax = fmaxf(tmax, __shfl_xor_sync(0xffffffffu, tmax, off));
            float nm = fmaxf(m_[i], tmax);
            float al = __expf(m_[i] - nm);
            float ts = 0.f;
            #pragma unroll
            for (int j = 0; j < 4; j++) {
                s[i][j] = __expf(s[i][j] - nm);
                ts += s[i][j];
            }
            #pragma unroll
            for (int off = 8; off >= 1; off >>= 1)
                ts += __shfl_xor_sync(0xffffffffu, ts, off);
            l_[i] = l_[i] * al + ts;
            m_[i] = nm;
            #pragma unroll
            for (int c = 0; c < 4; c++) o[i][c] *= al;
            #pragma unroll
            for (int j = 0; j < 4; j++)
                Ps[(ty * 4 + i) * PAD + tx * 4 + j] = s[i][j];
        }
        __syncthreads();

        // O += P @ V   (O cols = d = tx*4+c)
        #pragma unroll 8
        for (int j = 0; j < 64; j++) {
            float a0 = Ps[(ty * 4 + 0) * PAD + j];
            float a1 = Ps[(ty * 4 + 1) * PAD + j];
            float a2 = Ps[(ty * 4 + 2) * PAD + j];
            float a3 = Ps[(ty * 4 + 3) * PAD + j];
            float b0 = Vs[j * PAD + tx * 4 + 0];
            float b1 = Vs[j * PAD + tx * 4 + 1];
            float b2 = Vs[j * PAD + tx * 4 + 2];
            float b3 = Vs[j * PAD + tx * 4 + 3];
            o[0][0] += a0 * b0; o[0][1] += a0 * b1; o[0][2] += a0 * b2; o[0][3] += a0 * b3;
            o[1][0] += a1 * b0; o[1][1] += a1 * b1; o[1][2] += a1 * b2; o[1][3] += a1 * b3;
            o[2][0] += a2 * b0; o[2][1] += a2 * b1; o[2][2] += a2 * b2; o[2][3] += a2 * b3;
            o[3][0] += a3 * b0; o[3][1] += a3 * b1; o[3][2] += a3 * b2; o[3][3] += a3 * b3;
        }
        __syncthreads();
    }

    // write x in (B, L, H*D) layout
    #pragma unroll
    for (int i = 0; i < 4; i++) {
        float inv = 1.0f / l_[i];
        int qrow = qt * 64 + ty * 4 + i;
        float4 val;
        val.x = o[i][0] * inv; val.y = o[i][1] * inv;
        val.z = o[i][2] * inv; val.w = o[i][3] * inv;
        *(float4*)&x[((size_t)(b * LL + qrow)) * (HH * DD) + h * DD + tx * 4] = val;
    }
}

// ---------------------------------------------------------------------------
extern "C" void kernel_launch(void* const* d_in, const int* in_sizes, int n_in,
                              void* d_out, int out_size)
{
    const float* inq  = (const float*)d_in[0];
    const float* inkv = (const float*)d_in[1];
    const float* Wq   = (const float*)d_in[2];
    const float* bq   = (const float*)d_in[3];
    const float* Wk   = (const float*)d_in[4];
    const float* bk   = (const float*)d_in[5];
    const float* Wv   = (const float*)d_in[6];
    const float* bv   = (const float*)d_in[7];
    const float* Wo   = (const float*)d_in[8];
    const float* bo   = (const float*)d_in[9];
    const float* toep = (const float*)d_in[10];
    float* out = (float*)d_out;

    float *pq, *pk, *pv, *px;
    cudaGetSymbolAddress((void**)&pq, g_q);
    cudaGetSymbolAddress((void**)&pk, g_k);
    cudaGetSymbolAddress((void**)&pv, g_v);
    cudaGetSymbolAddress((void**)&px, g_x);

    const int M = BB * LL;      // 16384
    const int N = HH * DD;      // 512
    const int K = FF;           // 512

    dim3 gg(N / 128, M / 128); // (4, 128)

    gemm_kernel<<<gg, 256>>>(inq,  Wq, bq, pq, M, N, K, 1);
    gemm_kernel<<<gg, 256>>>(inkv, Wk, bk, pk, M, N, K, 1);
    gemm_kernel<<<gg, 256>>>(inkv, Wv, bv, pv, M, N, K, 1);

    size_t smem = (size_t)(4 * 64 * PAD + 4096) * sizeof(float);  // 82944 B
    cudaFuncSetAttribute(attn_kernel, cudaFuncAttributeMaxDynamicSharedMemorySize, (int)smem);
    attn_kernel<<<dim3(LL / 64, HH, BB), 256, smem>>>(pq, pk, pv, toep, px);

    gemm_kernel<<<gg, 256>>>(px, Wo, bo, out, M, FF, N, 0);
}